// round 17
// baseline (speedup 1.0000x reference)
#include <cuda_runtime.h>
#include <math.h>

#define NE   16
#define NU   8
#define NA   4
#define NSV  256
#define NPV  32
#define NFB  4
#define NDET 16
#define SVOUT 832
#define S0IN  56
#define NLAY 5
#define MAXB 2048

// ---- global scratch (static __device__, allowed) ----
__device__ float g_sv[(size_t)MAXB*NE*NSV];            // [b][e][256]
__device__ float g_pp[(size_t)MAXB*NLAY*NE*64];        // [b][l][e][pu32|pd32]
__device__ float g_mumd[(size_t)MAXB*2*NSV];           // [b][mu256|md256]
__device__ float g_gg4[4][(size_t)MAXB*NSV];           // k-split gg partials
__device__ float g_env[(size_t)MAXB*NE];

// packed f32x2 helpers (sm_103a)
#define FFMA2(acc, s2, w2) \
    asm("fma.rn.f32x2 %0, %1, %2, %0;" : "+l"(acc) : "l"(s2), "l"(w2))
#define SPLAT(d, f) \
    asm("mov.b64 %0, {%1, %1};" : "=l"(d) : "r"(__float_as_uint(f)))

// ======================= P: per-walker prep + p-stream =======================
__global__ __launch_bounds__(256, 2)
void prep_kernel(const float* __restrict__ r,   const float* __restrict__ a,
                 const float* __restrict__ sW0, const float* __restrict__ sb0,
                 const float* __restrict__ pW0, const float* __restrict__ pb0,
                 const float* __restrict__ pW,  const float* __restrict__ pb)
{
    __shared__ __align__(16) float s_blk0[NE][S0IN];
    __shared__ __align__(16) float s_pw[NPV*NPV];
    __shared__ float s_pb[NPV];
    __shared__ float s_pu0[NE][4], s_pd0[NE][4];
    __shared__ float s_r[NE][3], s_a[NA][3];
    __shared__ __align__(16) float s_pp[NE][64];

    const int tid = threadIdx.x;
    const int b   = blockIdx.x;

    if (tid < NE*3) ((float*)s_r)[tid] = r[b*NE*3 + tid];
    if (tid < NA*3) ((float*)s_a)[tid] = a[tid];
    if (tid < 64) { int e=tid>>2, c=tid&3; s_pu0[e][c]=0.f; s_pd0[e][c]=0.f; }
    __syncthreads();

    // ra features -> blk0 cols [0,16)
    if (tid < NE*NA) {
        int e = tid >> 2, at = tid & 3;
        float dx = s_r[e][0]-s_a[at][0];
        float dy = s_r[e][1]-s_a[at][1];
        float dz = s_r[e][2]-s_a[at][2];
        float len = sqrtf(dx*dx+dy*dy+dz*dz);
        s_blk0[e][at*4+0]=dx; s_blk0[e][at*4+1]=dy;
        s_blk0[e][at*4+2]=dz; s_blk0[e][at*4+3]=len;
    }
    // pair features
    const int pi = tid >> 4;
    const int pj = tid & 15;
    float p0[4];
    {
        float dx = s_r[pj][0]-s_r[pi][0];
        float dy = s_r[pj][1]-s_r[pi][1];
        float dz = s_r[pj][2]-s_r[pi][2];
        float ax=dx, ay=dy, az=dz;
        if (pi==pj) { ax+=1.f; ay+=1.f; az+=1.f; }
        p0[0]=dx; p0[1]=dy; p0[2]=dz; p0[3]=sqrtf(ax*ax+ay*ay+az*az);
    }
    __syncthreads();

    // envelope
    if (tid < NE) {
        float s=0.f;
        #pragma unroll
        for (int at=0; at<NA; ++at) s += expf(-s_blk0[tid][at*4+3]);
        g_env[(size_t)b*NE + tid] = s;
    }
    // mu0/md0 -> blk0 cols [16,48)
    if (tid < 16) {
        float mu=0.f, md=0.f;
        for (int e=0;e<8;e++)  mu += s_blk0[e][tid];
        for (int e=8;e<16;e++) md += s_blk0[e][tid];
        mu *= 0.125f; md *= 0.125f;
        for (int e=0;e<NE;e++){ s_blk0[e][16+tid]=mu; s_blk0[e][32+tid]=md; }
    }
    // raw p means
    {
        float* dst = (pi<NU) ? &s_pu0[pj][0] : &s_pd0[pj][0];
        #pragma unroll
        for (int c=0;c<4;c++) atomicAdd(&dst[c], p0[c]*0.125f);
    }
    if (tid < 128) s_pw[tid] = pW0[tid];
    if (tid < NPV) s_pb[tid] = pb0[tid];
    __syncthreads();
    if (tid < 64) {
        int e=tid>>2, c=tid&3;
        s_blk0[e][48+c]=s_pu0[e][c];
        s_blk0[e][52+c]=s_pd0[e][c];
    }
    __syncthreads();

    // p layer 0
    float pv[NPV];
    {
        #pragma unroll
        for (int c=0;c<NPV;c++) pv[c]=s_pb[c];
        #pragma unroll
        for (int k=0;k<4;k++) {
            float aa = p0[k];
            #pragma unroll
            for (int c=0;c<NPV;c++) pv[c] += aa*s_pw[k*NPV+c];
        }
        #pragma unroll
        for (int c=0;c<NPV;c++) pv[c]=tanhf(pv[c]);
    }

    // s layer 0: col tid, all electrons in registers; write sv + mu/md
    {
        const int j = tid;
        float a0[NE];
        float bb = sb0[j];
        #pragma unroll
        for (int e=0;e<NE;e++) a0[e]=bb;
        for (int k=0;k<S0IN;k++) {
            float w = sW0[k*NSV+j];
            #pragma unroll
            for (int e=0;e<NE;e++) a0[e] += s_blk0[e][k]*w;
        }
        float mu=0.f, md=0.f;
        #pragma unroll
        for (int e=0;e<NE;e++) {
            float t = tanhf(a0[e]);
            g_sv[((size_t)b*NE + e)*NSV + j] = t;
            if (e<8) mu += t; else md += t;
        }
        g_mumd[(size_t)b*2*NSV + j]       = mu*0.125f;
        g_mumd[(size_t)b*2*NSV + NSV + j] = md*0.125f;
    }

    // p-stream: per layer snapshot means -> global, then update pv
    for (int i=0; i<NLAY; ++i) {
        float4 z4 = make_float4(0.f,0.f,0.f,0.f);
        ((float4*)s_pp)[tid] = z4;          // 256 float4 = 16x64
        __syncthreads();
        {
            float* dst = &s_pp[pj][(pi<NU)?0:32];
            #pragma unroll
            for (int c=0;c<NPV;c++) atomicAdd(&dst[c], pv[c]*0.125f);
        }
        __syncthreads();
        ((float4*)(g_pp + ((size_t)b*NLAY + i)*NE*64))[tid] = ((const float4*)s_pp)[tid];
        if (i < NFB) {
            #pragma unroll
            for (int q=0;q<4;q++) s_pw[tid+q*256] = pW[i*NPV*NPV + tid + q*256];
            if (tid<NPV) s_pb[tid]=pb[i*NPV+tid];
            __syncthreads();
            float pn[NPV];
            #pragma unroll
            for (int c=0;c<NPV;c++) pn[c]=s_pb[c];
            #pragma unroll
            for (int k=0;k<NPV;k++) {
                float aa=pv[k];
                #pragma unroll
                for (int c=0;c<NPV;c+=4) {
                    float4 w4 = *(const float4*)&s_pw[k*NPV+c];
                    pn[c]+=aa*w4.x; pn[c+1]+=aa*w4.y; pn[c+2]+=aa*w4.z; pn[c+3]+=aa*w4.w;
                }
            }
            #pragma unroll
            for (int c=0;c<NPV;c++) pv[c]=tanhf(pn[c])+pv[c];
        }
    }
}

// ======================= G: batched mu/md GEMM (rows 256..768) =======================
// grid = (B/32, 4). CTA: 32 walkers x 256 cols, k-slice 128 of 512.
__global__ __launch_bounds__(256, 4)
void gmean_kernel(const float* __restrict__ W, int B)
{
    __shared__ __align__(16) float s_act[32][128];  // 16 KB
    __shared__ __align__(16) float s_w[16][NSV];    // 16 KB
    const int tid = threadIdx.x;
    const int b0  = blockIdx.x * 32;
    const int ks  = blockIdx.y;

    // load activations (32 walkers x 128 k)
    #pragma unroll
    for (int q=0;q<4;q++) {
        int idx = tid + q*256;          // 1024 float4
        int w = idx >> 5, o = (idx & 31)*4;
        int bw = b0 + w; if (bw >= B) bw = B-1;
        *(float4*)&s_act[w][o] = *(const float4*)&g_mumd[(size_t)bw*2*NSV + ks*128 + o];
    }

    const int wg = tid >> 6;            // 4 groups of 8 walkers
    const int j4 = (tid & 63) * 4;
    float acc[8][4];
    #pragma unroll
    for (int i=0;i<8;i++){acc[i][0]=0.f;acc[i][1]=0.f;acc[i][2]=0.f;acc[i][3]=0.f;}

    for (int s=0;s<8;s++) {
        __syncthreads();
        #pragma unroll
        for (int q=0;q<4;q++) {
            int idx = tid + q*256;
            int row = idx >> 6, c4 = (idx & 63)*4;
            *(float4*)&s_w[row][c4] =
                *(const float4*)&W[(size_t)(NSV + ks*128 + s*16 + row)*NSV + c4];
        }
        __syncthreads();
        #pragma unroll
        for (int kk=0;kk<16;kk+=4) {
            float4 w0 = *(const float4*)&s_w[kk+0][j4];
            float4 w1 = *(const float4*)&s_w[kk+1][j4];
            float4 w2 = *(const float4*)&s_w[kk+2][j4];
            float4 w3 = *(const float4*)&s_w[kk+3][j4];
            #pragma unroll
            for (int i=0;i<8;i++) {
                float4 a4 = *(const float4*)&s_act[wg*8+i][s*16+kk];
                acc[i][0] = fmaf(a4.x,w0.x,fmaf(a4.y,w1.x,fmaf(a4.z,w2.x,fmaf(a4.w,w3.x,acc[i][0]))));
                acc[i][1] = fmaf(a4.x,w0.y,fmaf(a4.y,w1.y,fmaf(a4.z,w2.y,fmaf(a4.w,w3.y,acc[i][1]))));
                acc[i][2] = fmaf(a4.x,w0.z,fmaf(a4.y,w1.z,fmaf(a4.z,w2.z,fmaf(a4.w,w3.z,acc[i][2]))));
                acc[i][3] = fmaf(a4.x,w0.w,fmaf(a4.y,w1.w,fmaf(a4.z,w2.w,fmaf(a4.w,w3.w,acc[i][3]))));
            }
        }
    }
    #pragma unroll
    for (int i=0;i<8;i++) {
        int bw = b0 + wg*8 + i;
        if (bw < B) {
            float4 v = make_float4(acc[i][0],acc[i][1],acc[i][2],acc[i][3]);
            *(float4*)&g_gg4[ks][(size_t)bw*NSV + j4] = v;
        }
    }
}

// ======================= S: per-walker s_v GEMM (rows 0..256 + pu/pd) =======================
struct __align__(16) SmemS {
    float part[4][NE][NSV];   // 64 KB
    float sv[NE][NSV];        // 16 KB
    float pp[NE][64];         // 4 KB
    float gg[NSV];            // 1 KB
};

__global__ __launch_bounds__(256, 2)
void slayer_kernel(const float* __restrict__ W, const float* __restrict__ bias,
                   int l, int resid)
{
    extern __shared__ __align__(16) char smraw[];
    SmemS* S = reinterpret_cast<SmemS*>(smraw);
    const int tid = threadIdx.x;
    const int b   = blockIdx.x;

    #pragma unroll
    for (int q=0;q<4;q++)
        ((float4*)S->sv)[tid + q*256] = ((const float4*)(g_sv + (size_t)b*NE*NSV))[tid + q*256];
    ((float4*)S->pp)[tid] = ((const float4*)(g_pp + ((size_t)b*NLAY + l)*NE*64))[tid];
    S->gg[tid] = g_gg4[0][(size_t)b*NSV+tid] + g_gg4[1][(size_t)b*NSV+tid]
               + g_gg4[2][(size_t)b*NSV+tid] + g_gg4[3][(size_t)b*NSV+tid]
               + bias[tid];
    __syncthreads();

    const int kg = tid >> 6;
    const int j4 = (tid & 63) * 4;

    unsigned long long acc0[NE], acc1[NE];
    #pragma unroll
    for (int e=0;e<NE;e++) { acc0[e]=0ull; acc1[e]=0ull; }

    // sv rows: kg owns k in [kg*64, kg*64+64)
    {
        const float* Wr0 = W + (size_t)(kg*64)*NSV + j4;
        const float* sv0 = &S->sv[0][kg*64];
        #pragma unroll 1
        for (int kk=0; kk<64; kk+=4) {
            const float* Wr = Wr0 + (size_t)kk*NSV;
            ulonglong2 w0 = *(const ulonglong2*)(Wr);
            ulonglong2 w1 = *(const ulonglong2*)(Wr +   NSV);
            ulonglong2 w2 = *(const ulonglong2*)(Wr + 2*NSV);
            ulonglong2 w3 = *(const ulonglong2*)(Wr + 3*NSV);
            #pragma unroll
            for (int e=0;e<NE;e++) {
                float4 s4 = *(const float4*)(sv0 + e*NSV + kk);
                unsigned long long t;
                SPLAT(t, s4.x); FFMA2(acc0[e], t, w0.x); FFMA2(acc1[e], t, w0.y);
                SPLAT(t, s4.y); FFMA2(acc0[e], t, w1.x); FFMA2(acc1[e], t, w1.y);
                SPLAT(t, s4.z); FFMA2(acc0[e], t, w2.x); FFMA2(acc1[e], t, w2.y);
                SPLAT(t, s4.w); FFMA2(acc0[e], t, w3.x); FFMA2(acc1[e], t, w3.y);
            }
        }
    }
    // pu/pd rows: kg owns 16 of 64 combined rows (weight rows 768 + kg*16 ..)
    {
        const int r0 = kg*16;
        const float* Wp0 = W + (size_t)(3*NSV + r0)*NSV + j4;
        #pragma unroll 1
        for (int kk=0; kk<16; kk+=4) {
            const float* Wr = Wp0 + (size_t)kk*NSV;
            ulonglong2 w0 = *(const ulonglong2*)(Wr);
            ulonglong2 w1 = *(const ulonglong2*)(Wr +   NSV);
            ulonglong2 w2 = *(const ulonglong2*)(Wr + 2*NSV);
            ulonglong2 w3 = *(const ulonglong2*)(Wr + 3*NSV);
            #pragma unroll
            for (int e=0;e<NE;e++) {
                float4 s4 = *(const float4*)&S->pp[e][r0 + kk];
                unsigned long long t;
                SPLAT(t, s4.x); FFMA2(acc0[e], t, w0.x); FFMA2(acc1[e], t, w0.y);
                SPLAT(t, s4.y); FFMA2(acc0[e], t, w1.x); FFMA2(acc1[e], t, w1.y);
                SPLAT(t, s4.z); FFMA2(acc0[e], t, w2.x); FFMA2(acc1[e], t, w2.y);
                SPLAT(t, s4.w); FFMA2(acc0[e], t, w3.x); FFMA2(acc1[e], t, w3.y);
            }
        }
    }
    #pragma unroll
    for (int e=0;e<NE;e++) {
        ulonglong2 v; v.x = acc0[e]; v.y = acc1[e];
        *(ulonglong2*)&S->part[kg][e][j4] = v;
    }
    __syncthreads();

    // final pass: thread owns (e = tid>>4, 16 cols)
    {
        const int fe = tid >> 4;
        const int fj = (tid & 15) * 16;
        float* gdst = g_sv + ((size_t)b*NE + fe)*NSV;
        #pragma unroll
        for (int c=0;c<16;c+=4) {
            float4 q0 = *(const float4*)&S->part[0][fe][fj+c];
            float4 q1 = *(const float4*)&S->part[1][fe][fj+c];
            float4 q2 = *(const float4*)&S->part[2][fe][fj+c];
            float4 q3 = *(const float4*)&S->part[3][fe][fj+c];
            float4 g  = *(const float4*)&S->gg[fj+c];
            float4 nv;
            nv.x = tanhf(q0.x+q1.x+q2.x+q3.x+g.x);
            nv.y = tanhf(q0.y+q1.y+q2.y+q3.y+g.y);
            nv.z = tanhf(q0.z+q1.z+q2.z+q3.z+g.z);
            nv.w = tanhf(q0.w+q1.w+q2.w+q3.w+g.w);
            if (resid) {
                float4 old = *(const float4*)&S->sv[fe][fj+c];
                nv.x+=old.x; nv.y+=old.y; nv.z+=old.z; nv.w+=old.w;
            }
            *(float4*)&S->sv[fe][fj+c] = nv;     // WAR safe: exclusive owner of these cols
            *(float4*)&gdst[fj+c] = nv;
        }
    }
    if (resid) {
        __syncthreads();
        float mu=0.f, md=0.f;
        #pragma unroll
        for (int e=0;e<8;e++)  mu += S->sv[e][tid];
        #pragma unroll
        for (int e=8;e<16;e++) md += S->sv[e][tid];
        g_mumd[(size_t)b*2*NSV + tid]       = mu*0.125f;
        g_mumd[(size_t)b*2*NSV + NSV + tid] = md*0.125f;
    }
}

// ======================= O: orbitals + slogdets + combine =======================
__global__ __launch_bounds__(256, 2)
void orb_kernel(const float* __restrict__ wuW, const float* __restrict__ wub,
                const float* __restrict__ wdW, const float* __restrict__ wdb,
                const float* __restrict__ wfW, float* __restrict__ out)
{
    __shared__ __align__(16) float s_sv[NE][NSV];
    __shared__ __align__(16) float s_sw[2][8][128];
    __shared__ float s_env[NE];
    __shared__ float s_dsign[32], s_dld[32];
    const int tid = threadIdx.x;
    const int b   = blockIdx.x;

    #pragma unroll
    for (int q=0;q<4;q++)
        ((float4*)s_sv)[tid + q*256] = ((const float4*)(g_sv + (size_t)b*NE*NSV))[tid + q*256];
    if (tid < NE) s_env[tid] = g_env[(size_t)b*NE + tid];
    __syncthreads();

    {
        const int spin = tid >> 7;
        const int t7   = tid & 127;
        const int ojg  = t7 >> 2;
        const int oeg  = t7 & 3;
        const int oj4  = ojg * 4;
        const float* Wo = spin? wdW : wuW;
        const float* bo = spin? wdb : wub;
        float4 b4 = *(const float4*)&bo[oj4];
        float oa[2][4];
        #pragma unroll
        for (int i=0;i<2;i++) { oa[i][0]=b4.x; oa[i][1]=b4.y; oa[i][2]=b4.z; oa[i][3]=b4.w; }
        const int ebase = spin*8 + oeg*2;
        for (int k=0;k<NSV;k+=4) {
            float4 w0 = *(const float4*)&Wo[(size_t)(k+0)*128 + oj4];
            float4 w1 = *(const float4*)&Wo[(size_t)(k+1)*128 + oj4];
            float4 w2 = *(const float4*)&Wo[(size_t)(k+2)*128 + oj4];
            float4 w3 = *(const float4*)&Wo[(size_t)(k+3)*128 + oj4];
            #pragma unroll
            for (int i=0;i<2;i++) {
                float4 s4 = *(const float4*)&s_sv[ebase+i][k];
                oa[i][0] = fmaf(s4.x,w0.x,fmaf(s4.y,w1.x,fmaf(s4.z,w2.x,fmaf(s4.w,w3.x,oa[i][0]))));
                oa[i][1] = fmaf(s4.x,w0.y,fmaf(s4.y,w1.y,fmaf(s4.z,w2.y,fmaf(s4.w,w3.y,oa[i][1]))));
                oa[i][2] = fmaf(s4.x,w0.z,fmaf(s4.y,w1.z,fmaf(s4.z,w2.z,fmaf(s4.w,w3.z,oa[i][2]))));
                oa[i][3] = fmaf(s4.x,w0.w,fmaf(s4.y,w1.w,fmaf(s4.z,w2.w,fmaf(s4.w,w3.w,oa[i][3]))));
            }
        }
        #pragma unroll
        for (int i=0;i<2;i++) {
            float4 v; v.x=oa[i][0]; v.y=oa[i][1]; v.z=oa[i][2]; v.w=oa[i][3];
            *(float4*)&s_sw[spin][oeg*2+i][oj4] = v;
        }
    }
    __syncthreads();

    if (tid < 32) {
        const int spin = tid>>4, d = tid&15;
        float M[8][8];
        for (int jr=0;jr<8;jr++)
            for (int ic=0;ic<8;ic++)
                M[jr][ic] = s_sw[spin][ic][jr*NDET+d] * s_env[spin*8+ic];
        float sign=1.f, ld=0.f;
        for (int k=0;k<8;k++) {
            int p=k; float mv=fabsf(M[k][k]);
            for (int rr2=k+1; rr2<8; rr2++) { float v=fabsf(M[rr2][k]); if (v>mv){mv=v;p=rr2;} }
            if (p!=k) { for (int c=0;c<8;c++){float t=M[k][c];M[k][c]=M[p][c];M[p][c]=t;} sign=-sign; }
            float piv = M[k][k];
            if (piv<0.f) sign=-sign;
            ld += logf(fabsf(piv));
            float inv = 1.f/piv;
            for (int rr2=k+1; rr2<8; rr2++) {
                float f = M[rr2][k]*inv;
                for (int c=k+1;c<8;c++) M[rr2][c] -= f*M[k][c];
            }
        }
        s_dsign[tid]=sign; s_dld[tid]=ld;
    }
    __syncthreads();

    if (tid==0) {
        float mmax=-INFINITY;
        float ldt[NDET], sg[NDET];
        #pragma unroll
        for (int d=0;d<NDET;d++) {
            ldt[d]=s_dld[d]+s_dld[16+d];
            sg[d] =s_dsign[d]*s_dsign[16+d];
            mmax = fmaxf(mmax, ldt[d]);
        }
        float psi=0.f;
        #pragma unroll
        for (int d=0;d<NDET;d++) psi += sg[d]*expf(ldt[d]-mmax)*wfW[d];
        out[b] = logf(fabsf(psi)) + mmax;
    }
}

extern "C" void kernel_launch(void* const* d_in, const int* in_sizes, int n_in,
                              void* d_out, int out_size) {
    const float* r   = (const float*)d_in[0];
    const float* a   = (const float*)d_in[1];
    const float* sW0 = (const float*)d_in[2];
    const float* sb0 = (const float*)d_in[3];
    const float* sW  = (const float*)d_in[4];
    const float* sb  = (const float*)d_in[5];
    const float* pW0 = (const float*)d_in[6];
    const float* pb0 = (const float*)d_in[7];
    const float* pW  = (const float*)d_in[8];
    const float* pb  = (const float*)d_in[9];
    const float* vW  = (const float*)d_in[10];
    const float* vb  = (const float*)d_in[11];
    const float* wuW = (const float*)d_in[12];
    const float* wub = (const float*)d_in[13];
    const float* wdW = (const float*)d_in[14];
    const float* wdb = (const float*)d_in[15];
    const float* wfW = (const float*)d_in[16];
    float* out = (float*)d_out;

    int B = in_sizes[0] / (NE*3);
    if (B > MAXB) B = MAXB;

    static int s_attr_done = 0;
    if (!s_attr_done) {
        cudaFuncSetAttribute(slayer_kernel,
                             cudaFuncAttributeMaxDynamicSharedMemorySize,
                             (int)sizeof(SmemS));
        s_attr_done = 1;
    }

    prep_kernel<<<B, 256>>>(r, a, sW0, sb0, pW0, pb0, pW, pb);
    int mtiles = (B + 31) / 32;
    for (int l=0; l<NLAY; ++l) {
        const float* W    = (l<NFB)? (sW + (size_t)l*SVOUT*NSV) : vW;
        const float* bias = (l<NFB)? (sb + l*NSV) : vb;
        gmean_kernel<<<dim3(mtiles,4), 256>>>(W, B);
        slayer_kernel<<<B, 256, (int)sizeof(SmemS)>>>(W, bias, l, (l<NFB)?1:0);
    }
    orb_kernel<<<B, 256>>>(wuW, wub, wdW, wdb, wfW, out);
}